// round 16
// baseline (speedup 1.0000x reference)
#include <cuda_runtime.h>
#include <cuda.h>
#include <cuda_fp16.h>

#define NF 512
#define NH 16
#define NC 40
#define NMAX 100000
#define EMAX 3200000

// ---- scratch (static device globals; no allocations allowed) ----
__device__ float  g_deg[NMAX];
__device__ float  g_dinv[NMAX];
__device__ __half g_h1h[NMAX * NH];   // dinv*h1 fp16 (layer-1 gather source)
__device__ float  g_a1[NMAX * NH];    // dinv*h1 fp32 (layer-1 self term)
__device__ __half g_a1sh[NMAX * NH];  // dinv*relu(...) fp16 (layer-2 gather source)
__device__ float  g_agg2[NMAX * NH];  // a1s fp32 (layer-2 self term)
// CSR
__device__ int    g_cnt[NMAX];
__device__ int    g_off[NMAX];
__device__ int    g_cur[NMAX];
__device__ int    g_bsum[512];
__device__ int    g_adj[EMAX];

// packed fp32x2 FMA (Blackwell, PTX 8.6)
#define FFMA2(acc, a, b) \
    asm("fma.rn.f32x2 %0, %1, %2, %3;" : "=l"(acc) : "l"(a), "l"(b), "l"(acc))
#define PACK2(out, lo, hi) \
    asm("mov.b64 %0, {%1, %2};" : "=l"(out) : "f"(lo), "f"(hi))
#define UNPACK2(lo, hi, in) \
    asm("mov.b64 {%0, %1}, %2;" : "=f"(lo), "=f"(hi) : "l"(in))

// ---- TMA / mbarrier helpers ----
__device__ __forceinline__ unsigned smem_u32(const void* p) {
    unsigned a;
    asm("{ .reg .u64 t; cvta.to.shared.u64 t, %1; cvt.u32.u64 %0, t; }"
        : "=r"(a) : "l"(p));
    return a;
}
#define MBAR_INIT(a, c) \
    asm volatile("mbarrier.init.shared.b64 [%0], %1;" :: "r"(a), "r"(c) : "memory")
#define MBAR_EXPECT_TX(a, b) \
    asm volatile("mbarrier.arrive.expect_tx.shared.b64 _, [%0], %1;" :: "r"(a), "r"(b) : "memory")
#define TMA_2D(sa, tm, cx, cy, mb) \
    asm volatile("cp.async.bulk.tensor.2d.shared::cta.global.tile.mbarrier::complete_tx::bytes " \
                 "[%0], [%1, {%2, %3}], [%4];" \
                 :: "r"(sa), "l"(tm), "r"(cx), "r"(cy), "r"(mb) : "memory")
#define MBAR_WAIT(a, par) \
    asm volatile("{\n\t.reg .pred p;\n\tWL_%=:\n\t" \
                 "mbarrier.try_wait.parity.acquire.cta.shared::cta.b64 p, [%0], %1;\n\t" \
                 "@!p bra WL_%=;\n\t}" :: "r"(a), "r"(par) : "memory")

__device__ __forceinline__ void h2acc(float4& acc, uint2 raw) {
    float2 f0 = __half22float2(*(__half2*)&raw.x);
    float2 f1 = __half22float2(*(__half2*)&raw.y);
    acc.x += f0.x; acc.y += f0.y; acc.z += f1.x; acc.w += f1.y;
}

// ---------------------------------------------------------------------------
__global__ void k_init(int n) {
    int i = blockIdx.x * blockDim.x + threadIdx.x;
    if (i < n) { g_deg[i] = 1.0f; g_cnt[i] = 0; }
}

// one edge pass: norm-degree over src (float) + in-degree over dst (int)
__global__ void k_count(const int* __restrict__ src,
                        const int* __restrict__ dst, int E) {
    int e = blockIdx.x * blockDim.x + threadIdx.x;
    if (e >= E) return;
    atomicAdd(&g_deg[src[e]], 1.0f);
    atomicAdd(&g_cnt[dst[e]], 1);
}

__global__ void k_scan1(int n) {
    __shared__ int sm[256];
    int t = threadIdx.x;
    int i = blockIdx.x * 256 + t;
    sm[t] = (i < n) ? g_cnt[i] : 0;
    __syncthreads();
#pragma unroll
    for (int o = 128; o > 0; o >>= 1) {
        if (t < o) sm[t] += sm[t + o];
        __syncthreads();
    }
    if (t == 0) g_bsum[blockIdx.x] = sm[0];
}

__global__ void k_scan2(int NB) {
    __shared__ int sm[512];
    int t = threadIdx.x;
    int v = (t < NB) ? g_bsum[t] : 0;
    sm[t] = v;
    __syncthreads();
#pragma unroll
    for (int o = 1; o < 512; o <<= 1) {
        int x = (t >= o) ? sm[t - o] : 0;
        __syncthreads();
        sm[t] += x;
        __syncthreads();
    }
    if (t < NB) g_bsum[t] = sm[t] - v;
}

__global__ void k_scan3(int n) {
    __shared__ int sm[256];
    int t = threadIdx.x;
    int i = blockIdx.x * 256 + t;
    int v = (i < n) ? g_cnt[i] : 0;
    sm[t] = v;
    __syncthreads();
#pragma unroll
    for (int o = 1; o < 256; o <<= 1) {
        int x = (t >= o) ? sm[t - o] : 0;
        __syncthreads();
        sm[t] += x;
        __syncthreads();
    }
    if (i < n) {
        int off = g_bsum[blockIdx.x] + sm[t] - v;
        g_off[i] = off;
        g_cur[i] = off;
    }
}

__global__ void k_scatter(const int* __restrict__ src,
                          const int* __restrict__ dst, int E) {
    int e = blockIdx.x * blockDim.x + threadIdx.x;
    if (e >= E) return;
    int p = atomicAdd(&g_cur[dst[e]], 1);
    g_adj[p] = src[e];
}

// ---------------------------------------------------------------------------
// GEMM1 (TMA) + FUSED dinv epilogue: deg is final before this runs, so the
// epilogue computes di = rsqrt(deg) and emits g_dinv, a1 = di*h (fp32 self),
// h1h = di*h (fp16 gather). No separate h1 write / dinv_scale pass.
// ---------------------------------------------------------------------------
#define TILE_K 32
#define GROWS 256
#define BUF_FLOATS (GROWS * TILE_K)
#define GEMM1_SMEM ((NF * NH + 2 * BUF_FLOATS) * sizeof(float) + 64)

__global__ void __launch_bounds__(256, 2) k_gemm1(
    const __grid_constant__ CUtensorMap tmap,
    const float* __restrict__ W1,
    const float* __restrict__ b1, int n) {
    extern __shared__ __align__(1024) float smem[];
    float* sW = smem;
    float* buf = smem + NF * NH;
    unsigned long long* mbar = (unsigned long long*)(buf + 2 * BUF_FLOATS);
    int tid = threadIdx.x;
    int row0 = blockIdx.x * GROWS;
    int row = row0 + tid;

    {
        const float4* W4 = (const float4*)W1;
        float4* sW4 = (float4*)sW;
        for (int i = tid; i < NF * NH / 4; i += 256) sW4[i] = W4[i];
    }

    unsigned mb[2], ba[2];
    mb[0] = smem_u32(mbar); mb[1] = mb[0] + 8;
    ba[0] = smem_u32(buf);  ba[1] = smem_u32(buf + BUF_FLOATS);

    if (tid == 0) { MBAR_INIT(mb[0], 1); MBAR_INIT(mb[1], 1); }
    __syncthreads();
    if (tid == 0) {
        asm volatile("fence.proxy.async.shared::cta;" ::: "memory");
        const void* tm = (const void*)&tmap;
        MBAR_EXPECT_TX(mb[0], (unsigned)(BUF_FLOATS * 4));
        TMA_2D(ba[0], tm, 0, row0, mb[0]);
        MBAR_EXPECT_TX(mb[1], (unsigned)(BUF_FLOATS * 4));
        TMA_2D(ba[1], tm, TILE_K, row0, mb[1]);
    }

    unsigned long long acc[8];
#pragma unroll
    for (int j = 0; j < 8; j++) {
        float lo = __ldg(&b1[2 * j]), hi = __ldg(&b1[2 * j + 1]);
        PACK2(acc[j], lo, hi);
    }

    int rs = tid & 7;
    int ph[2] = {0, 0};

    for (int t = 0; t < NF / TILE_K; t++) {
        int b = t & 1;
        MBAR_WAIT(mb[b], ph[b]);
        ph[b] ^= 1;

        const float* bx = buf + b * BUF_FLOATS + tid * TILE_K;
#pragma unroll
        for (int c4 = 0; c4 < 8; c4++) {
            int phys = c4 ^ rs;
            float4 xv = *(const float4*)(bx + phys * 4);
            const ulonglong2* wkk =
                (const ulonglong2*)(sW + (size_t)(t * TILE_K + c4 * 4) * NH);
#pragma unroll
            for (int j = 0; j < 4; j++) {
                unsigned long long xx;
                float xs = (&xv.x)[j];
                PACK2(xx, xs, xs);
                ulonglong2 wa = wkk[j * 4 + 0];
                ulonglong2 wb = wkk[j * 4 + 1];
                ulonglong2 wc = wkk[j * 4 + 2];
                ulonglong2 wd = wkk[j * 4 + 3];
                FFMA2(acc[0], xx, wa.x); FFMA2(acc[1], xx, wa.y);
                FFMA2(acc[2], xx, wb.x); FFMA2(acc[3], xx, wb.y);
                FFMA2(acc[4], xx, wc.x); FFMA2(acc[5], xx, wc.y);
                FFMA2(acc[6], xx, wd.x); FFMA2(acc[7], xx, wd.y);
            }
        }
        __syncthreads();
        if (tid == 0 && t + 2 < NF / TILE_K) {
            const void* tm = (const void*)&tmap;
            MBAR_EXPECT_TX(mb[b], (unsigned)(BUF_FLOATS * 4));
            TMA_2D(ba[b], tm, (t + 2) * TILE_K, row0, mb[b]);
        }
    }

    if (row < n) {
        float di = rsqrtf(g_deg[row]);
        g_dinv[row] = di;
        float4* a = (float4*)(g_a1 + (size_t)row * NH);
        __half2 hh[8];
#pragma unroll
        for (int q = 0; q < 4; q++) {
            float l0, h0, l1, h1;
            UNPACK2(l0, h0, acc[2 * q]);
            UNPACK2(l1, h1, acc[2 * q + 1]);
            float4 sv = make_float4(di * l0, di * h0, di * l1, di * h1);
            a[q] = sv;
            hh[2 * q + 0] = __floats2half2_rn(sv.x, sv.y);
            hh[2 * q + 1] = __floats2half2_rn(sv.z, sv.w);
        }
        uint4* dstp = (uint4*)(g_h1h + (size_t)row * NH);
        dstp[0] = *(uint4*)&hh[0];
        dstp[1] = *(uint4*)&hh[4];
    }
}

// ---------------------------------------------------------------------------
// Pull layer 1 (MLP=4): warp per dst; fuses relu/scale epilogue.
// ---------------------------------------------------------------------------
__global__ void __launch_bounds__(256) k_pull1(int n) {
    int gw = (blockIdx.x * blockDim.x + threadIdx.x) >> 5;
    if (gw >= n) return;
    int lane = threadIdx.x & 31;
    int slot = lane >> 2, c4 = lane & 3;
    int beg = g_off[gw], cnt = g_cnt[gw];

    float4 acc = make_float4(0.f, 0.f, 0.f, 0.f);
    int i = slot;
    for (; i + 24 < cnt; i += 32) {
        const int* ap = g_adj + beg + i;
        int s0 = ap[0], s1 = ap[8], s2 = ap[16], s3 = ap[24];
        uint2 r0 = *(const uint2*)(g_h1h + (size_t)s0 * NH + c4 * 4);
        uint2 r1 = *(const uint2*)(g_h1h + (size_t)s1 * NH + c4 * 4);
        uint2 r2 = *(const uint2*)(g_h1h + (size_t)s2 * NH + c4 * 4);
        uint2 r3 = *(const uint2*)(g_h1h + (size_t)s3 * NH + c4 * 4);
        h2acc(acc, r0); h2acc(acc, r1); h2acc(acc, r2); h2acc(acc, r3);
    }
    for (; i < cnt; i += 8) {
        int s = g_adj[beg + i];
        uint2 r = *(const uint2*)(g_h1h + (size_t)s * NH + c4 * 4);
        h2acc(acc, r);
    }
#pragma unroll
    for (int o = 16; o >= 4; o >>= 1) {
        acc.x += __shfl_xor_sync(0xffffffffu, acc.x, o);
        acc.y += __shfl_xor_sync(0xffffffffu, acc.y, o);
        acc.z += __shfl_xor_sync(0xffffffffu, acc.z, o);
        acc.w += __shfl_xor_sync(0xffffffffu, acc.w, o);
    }
    if (lane < 4) {
        float di = g_dinv[gw];
        float4 self = ((const float4*)g_a1)[(size_t)gw * 4 + c4];
        float4 v = make_float4(
            di * fmaxf(di * (self.x + acc.x), 0.0f),
            di * fmaxf(di * (self.y + acc.y), 0.0f),
            di * fmaxf(di * (self.z + acc.z), 0.0f),
            di * fmaxf(di * (self.w + acc.w), 0.0f));
        ((float4*)g_agg2)[(size_t)gw * 4 + c4] = v;
        __half2 h0 = __floats2half2_rn(v.x, v.y);
        __half2 h1 = __floats2half2_rn(v.z, v.w);
        uint2 u;
        u.x = *(unsigned*)&h0; u.y = *(unsigned*)&h1;
        *(uint2*)(g_a1sh + (size_t)gw * NH + c4 * 4) = u;
    }
}

// ---------------------------------------------------------------------------
// Pull layer 2 + FUSED final: gather sum + nsum, then in-warp
// logits = ns*b2 + t@W2 -> log_softmax -> out. No separate final pass.
// ---------------------------------------------------------------------------
__global__ void __launch_bounds__(256) k_pull2f(const float* __restrict__ W2,
                                                const float* __restrict__ b2,
                                                float* __restrict__ out, int n) {
    __shared__ float sW[NH * NC];
    __shared__ float sb[NC];
    for (int i = threadIdx.x; i < NH * NC; i += blockDim.x) sW[i] = W2[i];
    if (threadIdx.x < NC) sb[threadIdx.x] = b2[threadIdx.x];
    __syncthreads();

    int gw = (blockIdx.x * blockDim.x + threadIdx.x) >> 5;
    if (gw >= n) return;
    int lane = threadIdx.x & 31;
    int slot = lane >> 2, c4 = lane & 3;
    int beg = g_off[gw], cnt = g_cnt[gw];

    float4 acc = make_float4(0.f, 0.f, 0.f, 0.f);
    float accn = 0.0f;
    int i = slot;
    for (; i + 24 < cnt; i += 32) {
        const int* ap = g_adj + beg + i;
        int s0 = ap[0], s1 = ap[8], s2 = ap[16], s3 = ap[24];
        uint2 r0 = *(const uint2*)(g_a1sh + (size_t)s0 * NH + c4 * 4);
        uint2 r1 = *(const uint2*)(g_a1sh + (size_t)s1 * NH + c4 * 4);
        uint2 r2 = *(const uint2*)(g_a1sh + (size_t)s2 * NH + c4 * 4);
        uint2 r3 = *(const uint2*)(g_a1sh + (size_t)s3 * NH + c4 * 4);
        if (c4 == 0)
            accn += g_dinv[s0] + g_dinv[s1] + g_dinv[s2] + g_dinv[s3];
        h2acc(acc, r0); h2acc(acc, r1); h2acc(acc, r2); h2acc(acc, r3);
    }
    for (; i < cnt; i += 8) {
        int s = g_adj[beg + i];
        uint2 r = *(const uint2*)(g_a1sh + (size_t)s * NH + c4 * 4);
        if (c4 == 0) accn += g_dinv[s];
        h2acc(acc, r);
    }
#pragma unroll
    for (int o = 16; o >= 4; o >>= 1) {
        acc.x += __shfl_xor_sync(0xffffffffu, acc.x, o);
        acc.y += __shfl_xor_sync(0xffffffffu, acc.y, o);
        acc.z += __shfl_xor_sync(0xffffffffu, acc.z, o);
        acc.w += __shfl_xor_sync(0xffffffffu, acc.w, o);
        accn  += __shfl_xor_sync(0xffffffffu, accn, o);
    }

    // every lane: its c4 quad of t = di*(self + acc)
    float di = g_dinv[gw];
    float4 self = ((const float4*)g_agg2)[(size_t)gw * 4 + c4];
    float4 tq = make_float4(di * (self.x + acc.x), di * (self.y + acc.y),
                            di * (self.z + acc.z), di * (self.w + acc.w));
    float ns = di * (di + __shfl_sync(0xffffffffu, accn, 0));

    // broadcast all 16 t values to every lane (source lanes 0..3 hold c4=0..3)
    float t[NH];
#pragma unroll
    for (int q = 0; q < 4; q++) {
        t[q * 4 + 0] = __shfl_sync(0xffffffffu, tq.x, q);
        t[q * 4 + 1] = __shfl_sync(0xffffffffu, tq.y, q);
        t[q * 4 + 2] = __shfl_sync(0xffffffffu, tq.z, q);
        t[q * 4 + 3] = __shfl_sync(0xffffffffu, tq.w, q);
    }

    // logits: lane c handles col c (all 32) and col 32+c (c<8)
    float v0 = ns * sb[lane];
    float v1 = (lane < 8) ? ns * sb[32 + lane] : -1e30f;
#pragma unroll
    for (int k = 0; k < NH; k++) {
        v0 += t[k] * sW[k * NC + lane];
        if (lane < 8) v1 += t[k] * sW[k * NC + 32 + lane];
    }

    float m = fmaxf(v0, v1);
#pragma unroll
    for (int o = 16; o > 0; o >>= 1) m = fmaxf(m, __shfl_xor_sync(0xffffffffu, m, o));
    float s = expf(v0 - m) + ((lane < 8) ? expf(v1 - m) : 0.0f);
#pragma unroll
    for (int o = 16; o > 0; o >>= 1) s += __shfl_xor_sync(0xffffffffu, s, o);
    float lse = m + logf(s);

    float* orow = out + (size_t)gw * NC;
    orow[lane] = v0 - lse;
    if (lane < 8) orow[32 + lane] = v1 - lse;
}

// ---------------------------------------------------------------------------
typedef CUresult (CUDAAPI *PFN_tmapEncode)(
    CUtensorMap*, CUtensorMapDataType, cuuint32_t, void*,
    const cuuint64_t*, const cuuint64_t*, const cuuint32_t*, const cuuint32_t*,
    CUtensorMapInterleave, CUtensorMapSwizzle, CUtensorMapL2promotion,
    CUtensorMapFloatOOBfill);

static cudaStream_t g_s2 = nullptr;
static cudaEvent_t g_eCnt = nullptr, g_eCSR = nullptr;
static PFN_tmapEncode g_encode = nullptr;

extern "C" void kernel_launch(void* const* d_in, const int* in_sizes, int n_in,
                              void* d_out, int out_size) {
    const float* x = (const float*)d_in[0];
    const int* ei = (const int*)d_in[1];     // int32 (JAX x64 disabled)
    const float* W1 = (const float*)d_in[2];
    const float* b1 = (const float*)d_in[3];
    const float* W2 = (const float*)d_in[4];
    const float* b2 = (const float*)d_in[5];
    float* out = (float*)d_out;

    int n = in_sizes[0] / NF;            // 100000
    int E = in_sizes[1] / 2;             // 3200000
    const int* src = ei;
    const int* dst = ei + E;

    cudaFuncSetAttribute(k_gemm1, cudaFuncAttributeMaxDynamicSharedMemorySize,
                         (int)GEMM1_SMEM);
    if (!g_s2) {
        cudaStreamCreateWithFlags(&g_s2, cudaStreamNonBlocking);
        cudaEventCreateWithFlags(&g_eCnt, cudaEventDisableTiming);
        cudaEventCreateWithFlags(&g_eCSR, cudaEventDisableTiming);
        cudaDriverEntryPointQueryResult qr;
        cudaGetDriverEntryPointByVersion("cuTensorMapEncodeTiled",
                                         (void**)&g_encode, 12000,
                                         cudaEnableDefault, &qr);
    }

    CUtensorMap tmap;
    {
        cuuint64_t dims[2] = {(cuuint64_t)NF, (cuuint64_t)n};
        cuuint64_t strides[1] = {(cuuint64_t)NF * sizeof(float)};
        cuuint32_t box[2] = {TILE_K, GROWS};
        cuuint32_t estr[2] = {1, 1};
        g_encode(&tmap, CU_TENSOR_MAP_DATA_TYPE_FLOAT32, 2, (void*)x,
                 dims, strides, box, estr,
                 CU_TENSOR_MAP_INTERLEAVE_NONE, CU_TENSOR_MAP_SWIZZLE_128B,
                 CU_TENSOR_MAP_L2_PROMOTION_L2_128B,
                 CU_TENSOR_MAP_FLOAT_OOB_FILL_NONE);
    }

    const int B = 256;
    int NB = (n + B - 1) / B;
    cudaStream_t s0 = 0;

    k_init<<<NB, B, 0, s0>>>(n);                              // #1
    k_count<<<(E + B - 1) / B, B, 0, s0>>>(src, dst, E);      // #2 (deg final)
    cudaEventRecord(g_eCnt, s0);

    // CSR scan+scatter on side stream (independent of gemm1)
    cudaStreamWaitEvent(g_s2, g_eCnt, 0);
    k_scan1<<<NB, B, 0, g_s2>>>(n);                           // #3

    // #4 (profiled): gemm1 + fused dinv epilogue (needs deg; count is done)
    k_gemm1<<<(n + GROWS - 1) / GROWS, 256, GEMM1_SMEM, s0>>>(tmap, W1, b1, n);

    k_scan2<<<1, 512, 0, g_s2>>>(NB);                         // #5
    k_scan3<<<NB, B, 0, g_s2>>>(n);                           // #6
    k_scatter<<<(E + B - 1) / B, B, 0, g_s2>>>(src, dst, E);  // #7
    cudaEventRecord(g_eCSR, g_s2);

    cudaStreamWaitEvent(s0, g_eCSR, 0);
    k_pull1<<<(n * 32 + B - 1) / B, B, 0, s0>>>(n);           // #8
    k_pull2f<<<(n * 32 + B - 1) / B, B, 0, s0>>>(W2, b2, out, n);  // #9
}